// round 1
// baseline (speedup 1.0000x reference)
#include <cuda_runtime.h>
#include <cstdint>

#define NH 32     // hidden
#define RK 6      // rank
#define BB 256    // batch
#define TT 2048   // time
#define DI 64     // input dim
#define DO 32     // output dim

// 64 MB scratch for x_proj (+bias folded in). __device__ global: allocation-free.
__device__ float g_xp[(size_t)BB * TT * NH];

// Packed fp32x2 FMA (Blackwell): d = a*b + c elementwise on both halves.
__device__ __forceinline__ float2 fma2(const float2 a, const float2 b, const float2 c) {
    float2 d;
    asm("fma.rn.f32x2 %0, %1, %2, %3;"
        : "=l"(*(unsigned long long*)&d)
        : "l"(*(const unsigned long long*)&a),
          "l"(*(const unsigned long long*)&b),
          "l"(*(const unsigned long long*)&c));
    return d;
}

// ---------------------------------------------------------------------------
// Kernel 1: x_proj[b,t,n] = sum_i inputs[b,t,i]*W_in[n,i] + bias[n]
// Tile: 64 (b,t) rows per block, 256 threads. n = tid&31, rgroup = tid>>5
// handles 8 rows. u reads are warp-broadcast LDS (conflict-free); W staged
// through smem padded to 65 floats/row (conflict-free scalar LDS).
// ---------------------------------------------------------------------------
__global__ void __launch_bounds__(256) xproj_kernel(
    const float* __restrict__ inp, const float* __restrict__ Win,
    const float* __restrict__ bias)
{
    __shared__ float u[64 * DI];          // 16 KB
    __shared__ float Wsm[NH][DI + 1];     // 32 x 65, padded

    const int tid = threadIdx.x;

    // Stage W_in coalesced
    for (int idx = tid; idx < NH * DI; idx += 256)
        Wsm[idx / DI][idx % DI] = Win[idx];

    // Stage 64 input rows (contiguous 16 KB), coalesced float4
    const size_t base = (size_t)blockIdx.x * 64 * DI;
    const float4* gs = (const float4*)(inp + base);
    float4* sd = (float4*)u;
    #pragma unroll
    for (int k2 = 0; k2 < 4; k2++) sd[tid + 256 * k2] = gs[tid + 256 * k2];
    __syncthreads();

    const int n_ = tid & 31;
    const int rg = tid >> 5;

    // W row n_ -> registers as float2 pairs (conflict-free: bank = (n+i)%32)
    float2 w2[DI / 2];
    #pragma unroll
    for (int i = 0; i < DI; i += 2)
        w2[i / 2] = make_float2(Wsm[n_][i], Wsm[n_][i + 1]);

    float2 acc[8];
    #pragma unroll
    for (int r = 0; r < 8; r++) acc[r] = make_float2(0.f, 0.f);

    #pragma unroll
    for (int i4 = 0; i4 < DI / 4; i4++) {
        const float2 wlo = w2[2 * i4 + 0];
        const float2 whi = w2[2 * i4 + 1];
        #pragma unroll
        for (int r = 0; r < 8; r++) {
            const float4 u4 = *(const float4*)&u[(rg * 8 + r) * DI + i4 * 4];
            acc[r] = fma2(wlo, make_float2(u4.x, u4.y), acc[r]);
            acc[r] = fma2(whi, make_float2(u4.z, u4.w), acc[r]);
        }
    }

    const float bn = bias[n_];
    const size_t rowbase = (size_t)blockIdx.x * 64;
    #pragma unroll
    for (int r = 0; r < 8; r++)
        g_xp[(rowbase + rg * 8 + r) * NH + n_] = acc[r].x + acc[r].y + bn;
}

// ---------------------------------------------------------------------------
// Kernel 2: recurrence. One warp per batch element; lane l owns component l.
// Restructured so only v = tanh(pre) is broadcast each step:
//   p_t = W_rec h_t      : p <- 0.9 p + 0.1 * (W_rec v)
//   q_t = W_out h_{t+1}  : q <- 0.9 q + 0.1 * (W_out v)   (y_t = q_t + b_out)
//   h   <- 0.9 h + 0.1 v (for h_final only)
// ---------------------------------------------------------------------------
__global__ void __launch_bounds__(32) rnn_kernel(
    const float* __restrict__ m, const float* __restrict__ nv,
    const float* __restrict__ Mm, const float* __restrict__ Nm,
    const float* __restrict__ Wout, const float* __restrict__ bout,
    float* __restrict__ out, float* __restrict__ hfin)
{
    const int b = blockIdx.x;
    const int l = threadIdx.x;

    // Build W_rec row l from rank-7 factors, W_out row l (one-time)
    float Ml[RK];
    const float ml = m[l];
    #pragma unroll
    for (int j = 0; j < RK; j++) Ml[j] = Mm[l * RK + j];
    float wrec[NH], wout[NH];
    #pragma unroll
    for (int k = 0; k < NH; k++) {
        float s = ml * nv[k];
        #pragma unroll
        for (int j = 0; j < RK; j++) s = fmaf(Ml[j], Nm[k * RK + j], s);
        wrec[k] = s;
        wout[k] = Wout[l * NH + k];
    }
    const float bo = bout[l];

    const float* xp = g_xp + (size_t)b * TT * NH + l;
    float* yo = out + (size_t)b * TT * NH + l;

    const float ALPHA = 0.1f;
    const float OMA   = 1.0f - 0.1f;
    const float L2E2  = 2.885390081777926815f;  // 2*log2(e)

    float p = 0.f, q = 0.f, h = 0.f;

    // x prefetch ring, depth 4
    float xb[4];
    #pragma unroll
    for (int i = 0; i < 4; i++) xb[i] = xp[(size_t)i * NH];

    for (int t = 0; t < TT; t += 4) {
        #pragma unroll
        for (int s4 = 0; s4 < 4; s4++) {
            const int t0 = t + s4;
            const float x = xb[s4];
            const int tn = t0 + 4;
            if (tn < TT) xb[s4] = xp[(size_t)tn * NH];

            const float pre = p + x;
            // tanh(pre) = 1 - 2/(exp(2*pre)+1)  via ex2/rcp approx (~1e-7 abs)
            float e;
            asm("ex2.approx.f32 %0, %1;" : "=f"(e) : "f"(pre * L2E2));
            float r;
            asm("rcp.approx.f32 %0, %1;" : "=f"(r) : "f"(e + 1.0f));
            const float v = fmaf(-2.0f, r, 1.0f);

            float ap0 = 0.f, ap1 = 0.f, ap2 = 0.f, ap3 = 0.f;
            float aq0 = 0.f, aq1 = 0.f, aq2 = 0.f, aq3 = 0.f;
            #pragma unroll
            for (int k = 0; k < NH; k += 4) {
                const float v0 = __shfl_sync(0xffffffffu, v, k + 0);
                const float v1 = __shfl_sync(0xffffffffu, v, k + 1);
                const float v2 = __shfl_sync(0xffffffffu, v, k + 2);
                const float v3 = __shfl_sync(0xffffffffu, v, k + 3);
                ap0 = fmaf(wrec[k + 0], v0, ap0); aq0 = fmaf(wout[k + 0], v0, aq0);
                ap1 = fmaf(wrec[k + 1], v1, ap1); aq1 = fmaf(wout[k + 1], v1, aq1);
                ap2 = fmaf(wrec[k + 2], v2, ap2); aq2 = fmaf(wout[k + 2], v2, aq2);
                ap3 = fmaf(wrec[k + 3], v3, ap3); aq3 = fmaf(wout[k + 3], v3, aq3);
            }
            const float sp = (ap0 + ap1) + (ap2 + ap3);
            const float sq = (aq0 + aq1) + (aq2 + aq3);

            p = fmaf(OMA, p, ALPHA * sp);
            q = fmaf(OMA, q, ALPHA * sq);
            h = fmaf(OMA, h, ALPHA * v);

            yo[(size_t)t0 * NH] = q + bo;
        }
    }

    if (hfin) hfin[b * NH + l] = h;
}

// ---------------------------------------------------------------------------
extern "C" void kernel_launch(void* const* d_in, const int* in_sizes, int n_in,
                              void* d_out, int out_size) {
    const float* inputs = (const float*)d_in[0];
    const float* W_in   = (const float*)d_in[1];
    const float* m_     = (const float*)d_in[2];
    const float* n_     = (const float*)d_in[3];
    const float* M_     = (const float*)d_in[4];
    const float* Nm_    = (const float*)d_in[5];
    const float* bias   = (const float*)d_in[6];
    const float* Wout   = (const float*)d_in[7];
    const float* bout   = (const float*)d_in[8];

    float* out = (float*)d_out;
    float* hf = nullptr;
    const long long need = (long long)BB * TT * NH + (long long)BB * NH;
    if ((long long)out_size >= need)
        hf = out + (size_t)BB * TT * NH;

    xproj_kernel<<<BB * TT / 64, 256>>>(inputs, W_in, bias);
    rnn_kernel<<<BB, 32>>>(m_, n_, M_, Nm_, Wout, bout, out, hf);
}

// round 3
// speedup vs baseline: 1.4474x; 1.4474x over previous
#include <cuda_runtime.h>
#include <cstdint>

#define NH 32     // hidden
#define RK 6      // rank
#define BB 256    // batch
#define TT 2048   // time
#define DI 64     // input dim
#define DO 32     // output dim

// Scratch (device globals: allocation-free). 64 MB each.
__device__ float g_xp[(size_t)BB * TT * NH];   // pre-scaled x-projection: 2log2e*(u@W_in^T + bias)
__device__ float g_hs[(size_t)BB * TT * NH];   // hidden states h_{t+1}

// Packed fp32x2 ops (Blackwell)
__device__ __forceinline__ float2 fma2(const float2 a, const float2 b, const float2 c) {
    float2 d;
    asm("fma.rn.f32x2 %0, %1, %2, %3;"
        : "=l"(*(unsigned long long*)&d)
        : "l"(*(const unsigned long long*)&a),
          "l"(*(const unsigned long long*)&b),
          "l"(*(const unsigned long long*)&c));
    return d;
}
__device__ __forceinline__ float2 add2(const float2 a, const float2 b) {
    float2 d;
    asm("add.rn.f32x2 %0, %1, %2;"
        : "=l"(*(unsigned long long*)&d)
        : "l"(*(const unsigned long long*)&a),
          "l"(*(const unsigned long long*)&b));
    return d;
}

#define L2E2 2.885390081777926815f   // 2*log2(e)

// ---------------------------------------------------------------------------
// Kernel 1: g_xp[b,t,n] = L2E2 * (sum_i inputs[b,t,i]*W_in[n,i] + bias[n])
// ---------------------------------------------------------------------------
__global__ void __launch_bounds__(256) xproj_kernel(
    const float* __restrict__ inp, const float* __restrict__ Win,
    const float* __restrict__ bias)
{
    __shared__ float u[64 * DI];          // 16 KB
    __shared__ float Wsm[NH][DI + 1];     // padded

    const int tid = threadIdx.x;

    for (int idx = tid; idx < NH * DI; idx += 256)
        Wsm[idx / DI][idx % DI] = Win[idx];

    const size_t base = (size_t)blockIdx.x * 64 * DI;
    const float4* gs = (const float4*)(inp + base);
    float4* sd = (float4*)u;
    #pragma unroll
    for (int k2 = 0; k2 < 4; k2++) sd[tid + 256 * k2] = gs[tid + 256 * k2];
    __syncthreads();

    const int n_ = tid & 31;
    const int rg = tid >> 5;

    float2 w2[DI / 2];
    #pragma unroll
    for (int i = 0; i < DI; i += 2)
        w2[i / 2] = make_float2(Wsm[n_][i], Wsm[n_][i + 1]);

    float2 acc[8];
    #pragma unroll
    for (int r = 0; r < 8; r++) acc[r] = make_float2(0.f, 0.f);

    #pragma unroll
    for (int i4 = 0; i4 < DI / 4; i4++) {
        const float2 wlo = w2[2 * i4 + 0];
        const float2 whi = w2[2 * i4 + 1];
        #pragma unroll
        for (int r = 0; r < 8; r++) {
            const float4 u4 = *(const float4*)&u[(rg * 8 + r) * DI + i4 * 4];
            acc[r] = fma2(wlo, make_float2(u4.x, u4.y), acc[r]);
            acc[r] = fma2(whi, make_float2(u4.z, u4.w), acc[r]);
        }
    }

    const float bn = bias[n_];
    const size_t rowbase = (size_t)blockIdx.x * 64;
    #pragma unroll
    for (int r = 0; r < 8; r++)
        g_xp[(rowbase + rg * 8 + r) * NH + n_] = L2E2 * (acc[r].x + acc[r].y + bn);
}

// ---------------------------------------------------------------------------
// Kernel 2: sequential recurrence. One warp per batch; lane l owns unit l.
// State tracked in scaled space: p' = 2log2e * (W_rec h). Per step:
//   pre' = p' + x'            (x' pre-scaled)
//   v    = tanh(pre'/ (2log2e) * ...) = 1 - 2/(exp2(pre')+1)
//   p'  <- 0.9 p' + (0.1*2log2e*W_rec) v   (scale folded into wrec)
//   h   <- 0.9 h + 0.1 v ; store h   (outputs done later by epi GEMM)
// v broadcast via double-buffered smem + LDS.128 (no shuffles).
// ---------------------------------------------------------------------------
__global__ void __launch_bounds__(32) rnn_kernel(
    const float* __restrict__ m, const float* __restrict__ nv,
    const float* __restrict__ Mm, const float* __restrict__ Nm,
    float* __restrict__ hfin)
{
    __shared__ float4 vbuf[2][NH / 4];

    const int b = blockIdx.x;
    const int l = threadIdx.x;

    // Build scaled W_rec row l: wr[k] = 0.1 * 2log2e * (m_l n_k + sum_j M_lj N_kj)
    float Ml[RK];
    const float ml = m[l];
    #pragma unroll
    for (int j = 0; j < RK; j++) Ml[j] = Mm[l * RK + j];
    float wr[NH];
    #pragma unroll
    for (int k = 0; k < NH; k++) {
        float s = ml * nv[k];
        #pragma unroll
        for (int j = 0; j < RK; j++) s = fmaf(Ml[j], Nm[k * RK + j], s);
        wr[k] = 0.1f * L2E2 * s;
    }
    float2 w2[NH / 2];
    #pragma unroll
    for (int k = 0; k < NH; k += 2) w2[k / 2] = make_float2(wr[k], wr[k + 1]);

    const float* xp = g_xp + (size_t)b * TT * NH + l;
    float* hs = g_hs + (size_t)b * TT * NH + l;

    float p = 0.f, h = 0.f;

    float xb[4];
    #pragma unroll
    for (int i = 0; i < 4; i++) xb[i] = xp[(size_t)i * NH];

    for (int t = 0; t < TT; t += 4) {
        #pragma unroll
        for (int s4 = 0; s4 < 4; s4++) {
            const int t0 = t + s4;
            const int buf = s4 & 1;
            const float x = xb[s4];
            const int tn = t0 + 4;
            if (tn < TT) xb[s4] = xp[(size_t)tn * NH];

            const float pre = p + x;  // already scaled by 2log2e
            float e;
            asm("ex2.approx.f32 %0, %1;" : "=f"(e) : "f"(pre));
            float r;
            asm("rcp.approx.f32 %0, %1;" : "=f"(r) : "f"(e + 1.0f));
            const float v = fmaf(-2.0f, r, 1.0f);

            ((float*)vbuf[buf])[l] = v;
            __syncwarp();

            float2 a0 = make_float2(0.f, 0.f), a1 = a0, a2 = a0, a3 = a0;
            #pragma unroll
            for (int j = 0; j < NH / 4; j++) {
                const float4 v4 = vbuf[buf][j];
                float2 acc = (j & 3) == 0 ? a0 : (j & 3) == 1 ? a1 : (j & 3) == 2 ? a2 : a3;
                acc = fma2(w2[2 * j + 0], make_float2(v4.x, v4.y), acc);
                acc = fma2(w2[2 * j + 1], make_float2(v4.z, v4.w), acc);
                if ((j & 3) == 0) a0 = acc; else if ((j & 3) == 1) a1 = acc;
                else if ((j & 3) == 2) a2 = acc; else a3 = acc;
            }
            const float2 s01 = add2(a0, a1);
            const float2 s23 = add2(a2, a3);
            const float2 s = add2(s01, s23);
            const float sp = s.x + s.y;

            p = fmaf(0.9f, p, sp);           // 0.1*L2E2 folded into wr
            h = fmaf(0.9f, h, 0.1f * v);

            hs[(size_t)t0 * NH] = h;
        }
    }

    if (hfin) hfin[b * NH + l] = h;
}

// ---------------------------------------------------------------------------
// Kernel 3: epilogue GEMM  out[b,t,o] = sum_n hs[b,t,n]*W_out[o,n] + b_out[o]
// ---------------------------------------------------------------------------
__global__ void __launch_bounds__(256) epi_kernel(
    const float* __restrict__ Wout, const float* __restrict__ bout,
    float* __restrict__ out)
{
    __shared__ float hrow[64 * NH];       // 8 KB
    __shared__ float Wsm[DO][NH + 1];     // padded

    const int tid = threadIdx.x;

    for (int idx = tid; idx < DO * NH; idx += 256)
        Wsm[idx / NH][idx % NH] = Wout[idx];

    const size_t base = (size_t)blockIdx.x * 64 * NH;
    const float4* gs = (const float4*)(g_hs + base);
    float4* sd = (float4*)hrow;
    #pragma unroll
    for (int k2 = 0; k2 < 2; k2++) sd[tid + 256 * k2] = gs[tid + 256 * k2];
    __syncthreads();

    const int o = tid & 31;
    const int rg = tid >> 5;

    float2 w2[NH / 2];
    #pragma unroll
    for (int i = 0; i < NH; i += 2)
        w2[i / 2] = make_float2(Wsm[o][i], Wsm[o][i + 1]);

    float2 acc[8];
    #pragma unroll
    for (int r = 0; r < 8; r++) acc[r] = make_float2(0.f, 0.f);

    #pragma unroll
    for (int i4 = 0; i4 < NH / 4; i4++) {
        const float2 wlo = w2[2 * i4 + 0];
        const float2 whi = w2[2 * i4 + 1];
        #pragma unroll
        for (int r = 0; r < 8; r++) {
            const float4 h4 = *(const float4*)&hrow[(rg * 8 + r) * NH + i4 * 4];
            acc[r] = fma2(wlo, make_float2(h4.x, h4.y), acc[r]);
            acc[r] = fma2(whi, make_float2(h4.z, h4.w), acc[r]);
        }
    }

    const float bo = bout[o];
    const size_t rowbase = (size_t)blockIdx.x * 64;
    #pragma unroll
    for (int r = 0; r < 8; r++)
        out[(rowbase + rg * 8 + r) * DO + o] = acc[r].x + acc[r].y + bo;
}

// ---------------------------------------------------------------------------
extern "C" void kernel_launch(void* const* d_in, const int* in_sizes, int n_in,
                              void* d_out, int out_size) {
    const float* inputs = (const float*)d_in[0];
    const float* W_in   = (const float*)d_in[1];
    const float* m_     = (const float*)d_in[2];
    const float* n_     = (const float*)d_in[3];
    const float* M_     = (const float*)d_in[4];
    const float* Nm_    = (const float*)d_in[5];
    const float* bias   = (const float*)d_in[6];
    const float* Wout   = (const float*)d_in[7];
    const float* bout   = (const float*)d_in[8];

    float* out = (float*)d_out;
    float* hf = nullptr;
    const long long need = (long long)BB * TT * NH + (long long)BB * NH;
    if ((long long)out_size >= need)
        hf = out + (size_t)BB * TT * NH;

    xproj_kernel<<<BB * TT / 64, 256>>>(inputs, W_in, bias);
    rnn_kernel<<<BB, 32>>>(m_, n_, M_, Nm_, hf);
    epi_kernel<<<BB * TT / 64, 256>>>(Wout, bout, out);
}